// round 12
// baseline (speedup 1.0000x reference)
#include <cuda_runtime.h>
#include <cuda_bf16.h>

// Problem constants
#define TT   64
#define WW   88
#define HPc  48
#define CIN  53
#define HLc  12
#define G4   48
#define NHh  4
#define HDd  6
#define NUc  24
#define KK   25
#define NPX  (TT*WW)   // 5632
#define KVP  14        // K/V smem pitch (12 ch + 2 pad): odd float2-stride
#define UROWS 28
#define RPROWS 28

typedef unsigned long long u64;

// Scratch buffers (device globals)
__device__ float g_q0[NPX*NUc];
__device__ float g_k0[NPX*NUc];
__device__ float g_v0[NPX*NUc];
__device__ float g_q1[NPX*NUc];
__device__ float g_k1[NPX*NUc];
__device__ float g_v1[NPX*NUc];
__device__ float g_ao[NPX*NUc];   // attention output (pre-projection)

#define QSCALE 0.4082482904638631f

__device__ __forceinline__ float sigf(float x) {
    return __fdividef(1.0f, 1.0f + __expf(-x));
}
__device__ __forceinline__ float tanh_fast(float x) {
    return fmaf(2.0f, __fdividef(1.0f, 1.0f + __expf(-2.0f*x)), -1.0f);
}

// packed f32x2 helpers
__device__ __forceinline__ u64 pack2(float lo, float hi) {
    u64 r; asm("mov.b64 %0, {%1,%2};" : "=l"(r) : "f"(lo), "f"(hi)); return r;
}
__device__ __forceinline__ void unpack2(u64 v, float& lo, float& hi) {
    asm("mov.b64 {%0,%1}, %2;" : "=f"(lo), "=f"(hi) : "l"(v));
}
__device__ __forceinline__ u64 fma2(u64 a, u64 b, u64 c) {
    u64 d; asm("fma.rn.f32x2 %0, %1, %2, %3;" : "=l"(d) : "l"(a), "l"(b), "l"(c));
    return d;
}

// ---------------------------------------------------------------------------
// Fused LSTM + QKV(layer1). Block per sequence (w), 768 threads. (R9 version)
// ---------------------------------------------------------------------------
__global__ void __launch_bounds__(768)
lstm_kernel(const float* __restrict__ features,
            const int*   __restrict__ condition,
            const float* __restrict__ mask,
            const float* __restrict__ emb,
            const float* __restrict__ wih0, const float* __restrict__ whh0,
            const float* __restrict__ bih0, const float* __restrict__ bhh0,
            const float* __restrict__ wih1, const float* __restrict__ whh1,
            const float* __restrict__ bih1, const float* __restrict__ bhh1,
            const float* __restrict__ qkv_w,
            const float* __restrict__ qkv_b)
{
    const int w   = blockIdx.x;
    const int tid = threadIdx.x;

    __shared__ float xs  [TT][CIN];
    __shared__ float pre [TT][96];
    __shared__ float hbuf[TT][2*HLc];
    __shared__ float w0sh [96*CIN];
    __shared__ float wh0sh[96*HLc];
    __shared__ float w1sh [96*2*HLc];
    __shared__ float wh1sh[96*HLc];
    __shared__ float wqsh [72*NUc];
    __shared__ float b0sh[96], b1sh[96], bqsh[72];

    for (int idx = tid; idx < TT*CIN; idx += 768) {
        int t = idx / CIN, c = idx % CIN;
        float val;
        if (c < HPc)            val = features[(t*HPc + c)*WW + w];
        else if (c < HPc + 4)   val = emb[condition[t*WW + w]*4 + (c - HPc)];
        else                    val = mask[t*WW + w];
        xs[t][c] = val;
    }
    for (int x = tid; x < 96*CIN/4;   x += 768)
        ((float4*)w0sh)[x]  = ((const float4*)wih0)[x];
    for (int x = tid; x < 96*HLc/4;   x += 768)
        ((float4*)wh0sh)[x] = ((const float4*)whh0)[x];
    for (int x = tid; x < 96*2*HLc/4; x += 768)
        ((float4*)w1sh)[x]  = ((const float4*)wih1)[x];
    for (int x = tid; x < 96*HLc/4;   x += 768)
        ((float4*)wh1sh)[x] = ((const float4*)whh1)[x];
    for (int x = tid; x < 72*NUc/4;   x += 768)
        ((float4*)wqsh)[x]  = ((const float4*)qkv_w)[x];
    if (tid < 96) b0sh[tid] = bih0[tid] + bhh0[tid];
    if (tid < 96) b1sh[tid] = bih1[tid] + bhh1[tid];
    if (tid < 72) bqsh[tid] = qkv_b[tid];
    __syncthreads();

    {
        const int gate = tid % 96;
        const int tq   = tid / 96;
        float wr[CIN];
        #pragma unroll
        for (int c = 0; c < CIN; c++) wr[c] = w0sh[gate*CIN + c];
        const float b = b0sh[gate];
        for (int t = tq*8; t < tq*8 + 8; t++) {
            float a0 = b, a1 = 0.f, a2 = 0.f, a3 = 0.f;
            #pragma unroll
            for (int c = 0; c < 52; c += 4) {
                a0 = fmaf(xs[t][c+0], wr[c+0], a0);
                a1 = fmaf(xs[t][c+1], wr[c+1], a1);
                a2 = fmaf(xs[t][c+2], wr[c+2], a2);
                a3 = fmaf(xs[t][c+3], wr[c+3], a3);
            }
            a0 = fmaf(xs[t][52], wr[52], a0);
            pre[t][gate] = (a0 + a1) + (a2 + a3);
        }
    }
    __syncthreads();

    if (tid < 64) {
        const int dir = tid >> 5, u = tid & 31;
        float wi[HLc], wf[HLc], wg[HLc], wo[HLc];
        if (u < HLc) {
            #pragma unroll
            for (int c = 0; c < HLc; c++) {
                wi[c] = wh0sh[(dir*G4      + u)*HLc + c];
                wf[c] = wh0sh[(dir*G4 + 12 + u)*HLc + c];
                wg[c] = wh0sh[(dir*G4 + 24 + u)*HLc + c];
                wo[c] = wh0sh[(dir*G4 + 36 + u)*HLc + c];
            }
        } else {
            #pragma unroll
            for (int c = 0; c < HLc; c++) { wi[c]=wf[c]=wg[c]=wo[c]=0.f; }
        }
        float h = 0.f, cs = 0.f;
        for (int s = 0; s < TT; s++) {
            const int t = dir ? (TT - 1 - s) : s;
            float gi, gf, gg, go;
            if (u < HLc) {
                gi = pre[t][dir*G4      + u];
                gf = pre[t][dir*G4 + 12 + u];
                gg = pre[t][dir*G4 + 24 + u];
                go = pre[t][dir*G4 + 36 + u];
            } else { gi = gf = gg = go = 0.f; }
            #pragma unroll
            for (int c = 0; c < HLc; c++) {
                float hc = __shfl_sync(0xffffffffu, h, c);
                gi = fmaf(hc, wi[c], gi);
                gf = fmaf(hc, wf[c], gf);
                gg = fmaf(hc, wg[c], gg);
                go = fmaf(hc, wo[c], go);
            }
            cs = sigf(gf)*cs + sigf(gi)*tanh_fast(gg);
            h  = sigf(go)*tanh_fast(cs);
            if (u < HLc) hbuf[t][dir*HLc + u] = h;
        }
    }
    __syncthreads();

    {
        const int gate = tid % 96;
        const int tq   = tid / 96;
        float wr[2*HLc];
        #pragma unroll
        for (int c = 0; c < 2*HLc; c++) wr[c] = w1sh[gate*2*HLc + c];
        const float b = b1sh[gate];
        for (int t = tq*8; t < tq*8 + 8; t++) {
            float a0 = b, a1 = 0.f, a2 = 0.f, a3 = 0.f;
            #pragma unroll
            for (int c = 0; c < 2*HLc; c += 4) {
                a0 = fmaf(hbuf[t][c+0], wr[c+0], a0);
                a1 = fmaf(hbuf[t][c+1], wr[c+1], a1);
                a2 = fmaf(hbuf[t][c+2], wr[c+2], a2);
                a3 = fmaf(hbuf[t][c+3], wr[c+3], a3);
            }
            pre[t][gate] = (a0 + a1) + (a2 + a3);
        }
    }
    __syncthreads();

    if (tid < 64) {
        const int dir = tid >> 5, u = tid & 31;
        float wi[HLc], wf[HLc], wg[HLc], wo[HLc];
        if (u < HLc) {
            #pragma unroll
            for (int c = 0; c < HLc; c++) {
                wi[c] = wh1sh[(dir*G4      + u)*HLc + c];
                wf[c] = wh1sh[(dir*G4 + 12 + u)*HLc + c];
                wg[c] = wh1sh[(dir*G4 + 24 + u)*HLc + c];
                wo[c] = wh1sh[(dir*G4 + 36 + u)*HLc + c];
            }
        } else {
            #pragma unroll
            for (int c = 0; c < HLc; c++) { wi[c]=wf[c]=wg[c]=wo[c]=0.f; }
        }
        float h = 0.f, cs = 0.f;
        for (int s = 0; s < TT; s++) {
            const int t = dir ? (TT - 1 - s) : s;
            float gi, gf, gg, go;
            if (u < HLc) {
                gi = pre[t][dir*G4      + u];
                gf = pre[t][dir*G4 + 12 + u];
                gg = pre[t][dir*G4 + 24 + u];
                go = pre[t][dir*G4 + 36 + u];
            } else { gi = gf = gg = go = 0.f; }
            #pragma unroll
            for (int c = 0; c < HLc; c++) {
                float hc = __shfl_sync(0xffffffffu, h, c);
                gi = fmaf(hc, wi[c], gi);
                gf = fmaf(hc, wf[c], gf);
                gg = fmaf(hc, wg[c], gg);
                go = fmaf(hc, wo[c], go);
            }
            cs = sigf(gf)*cs + sigf(gi)*tanh_fast(gg);
            h  = sigf(go)*tanh_fast(cs);
            if (u < HLc) hbuf[t][dir*HLc + u] = h;
        }
    }
    __syncthreads();

    if (tid < 576) {
        const int oc = tid % 72;
        const int tq = tid / 72;
        float wr[NUc];
        #pragma unroll
        for (int c = 0; c < NUc; c++) wr[c] = wqsh[oc*NUc + c];
        const float b = bqsh[oc];
        const int e  = oc / NUc;
        const int ch = oc % NUc;
        const float scale = (e == 0) ? QSCALE : 1.0f;
        float* dst = (e == 0) ? g_q0 : (e == 1) ? g_k0 : g_v0;
        for (int t = tq*8; t < tq*8 + 8; t++) {
            float a0 = b, a1 = 0.f, a2 = 0.f, a3 = 0.f;
            #pragma unroll
            for (int c = 0; c < NUc; c += 4) {
                a0 = fmaf(hbuf[t][c+0], wr[c+0], a0);
                a1 = fmaf(hbuf[t][c+1], wr[c+1], a1);
                a2 = fmaf(hbuf[t][c+2], wr[c+2], a2);
                a3 = fmaf(hbuf[t][c+3], wr[c+3], a3);
            }
            dst[(t*WW + w)*NUc + ch] = ((a0 + a1) + (a2 + a3)) * scale;
        }
    }
}

// ---------------------------------------------------------------------------
// NATTEN-2D attention (head-split): block = (4x8 px tile, head-pair).
// Stages only 12 K/V channels -> ~111 KB smem -> 2 blocks/SM.
// 256 threads, 8 warps: warp = (row 0..3, head-in-pair 0..1), 8 queries/lane.
// Writes pre-projection attention output to g_ao.
// ---------------------------------------------------------------------------
__global__ void __launch_bounds__(256, 2)
natten_attn_kernel(const float* __restrict__ qsrc,
                   const float* __restrict__ ksrc,
                   const float* __restrict__ vsrc,
                   const float* __restrict__ rpb)
{
    const int i0 = blockIdx.y * 4;
    const int j0 = blockIdx.x * 8;
    const int hp = blockIdx.z;          // head pair 0/1
    extern __shared__ float sm[];
    float* ks   = sm;                           // [28*32][KVP]
    float* vs   = ks + UROWS*32*KVP;
    float* rpsh = vs + UROWS*32*KVP;            // [2][28][49]

    const int tid = threadIdx.x;

    const int si0 = min(max(i0     - 12, 0), TT - KK);
    const int si3 = min(max(i0 + 3 - 12, 0), TT - KK);
    const int nrows = si3 + KK - si0;                      // 25..28
    const int sj_min  = min(max(j0     - 12, 0), WW - KK);
    const int sj_last = min(max(j0 + 7 - 12, 0), WW - KK);
    const int ncols   = sj_last + KK - sj_min;             // <= 32
    const int rmin = si3 - (i0 + 3) + (KK - 1);

    // stage rpb for the 2 heads of this pair
    for (int idx = tid; idx < 2*RPROWS*49; idx += 256) {
        int hn = idx / (RPROWS*49);
        int rem = idx - hn*(RPROWS*49);
        int rr = rem / 49, cc = rem - rr*49;
        rpsh[idx] = __ldg(rpb + (hp*2 + hn)*2401 + (rmin + rr)*49 + cc);
    }

    // stage K/V: 12 channels for this head pair
    const int npx = nrows * 32;
    for (int spx = tid; spx < npx; spx += 256) {
        int c = spx & 31;
        int a = spx >> 5;
        int cc = min(c, ncols - 1);
        int gpx = (si0 + a)*WW + (sj_min + cc);
        const float4* kp = (const float4*)(ksrc + gpx*NUc + hp*12);
        const float4* vp = (const float4*)(vsrc + gpx*NUc + hp*12);
        float* kdst = ks + spx*KVP;
        float* vdst = vs + spx*KVP;
        #pragma unroll
        for (int f = 0; f < 3; f++) {
            float4 kd = kp[f];
            *(float2*)(kdst + f*4)     = make_float2(kd.x, kd.y);
            *(float2*)(kdst + f*4 + 2) = make_float2(kd.z, kd.w);
        }
        #pragma unroll
        for (int f = 0; f < 3; f++) {
            float4 vd = vp[f];
            *(float2*)(vdst + f*4)     = make_float2(vd.x, vd.y);
            *(float2*)(vdst + f*4 + 2) = make_float2(vd.z, vd.w);
        }
    }
    __syncthreads();

    const int warp = tid >> 5, lane = tid & 31;
    const int hi = warp & 1;            // head in pair
    const int r  = warp >> 1;           // row 0..3
    const int n  = hp*2 + hi;           // global head
    const int chb = hi*6;

    // rjp[p] = clamp(lane + A0 - p, 0, 48);  A0 = sj_min - j0 + 24
    const int A0 = sj_min - j0 + 24;
    // validity addend per query (0 or -1e4 folded into logit before exp)
    float vadd[8];
    #pragma unroll
    for (int p = 0; p < 8; p++) {
        int sj = min(max(j0 + p - 12, 0), WW - KK);
        int cb = sj - sj_min;
        vadd[p] = (((unsigned)(lane - cb)) < 25u) ? 0.f : -1e4f;
    }

    const int i = i0 + r;
    const int sir = min(max(i - 12, 0), TT - KK);
    const int arow = sir - si0;
    const int ra   = (sir - i + (KK - 1)) - rmin;
    const float* rpw = rpsh + hi*(RPROWS*49) + ra*49;

    // 8 query vectors packed in u64
    u64 q01[8], q23[8], q45[8];
    #pragma unroll
    for (int p = 0; p < 8; p++) {
        const u64* qp = (const u64*)(qsrc + ((i*WW + j0 + p)*NUc + n*HDd));
        q01[p] = qp[0]; q23[p] = qp[1]; q45[p] = qp[2];
    }

    float sum[8];
    u64 oa01[8], oa23[8], oa45[8];
    #pragma unroll
    for (int p = 0; p < 8; p++) {
        sum[p] = 0.f;
        oa01[p] = 0ULL; oa23[p] = 0ULL; oa45[p] = 0ULL;
    }

    const int lA0 = lane + A0;
    #pragma unroll 1
    for (int a = 0; a < KK; a++) {
        const int base = ((arow + a)*32 + lane)*KVP + chb;
        const u64* kp = (const u64*)(ks + base);
        const u64* vp = (const u64*)(vs + base);
        u64 k01 = kp[0], k23 = kp[1], k45 = kp[2];
        u64 v01 = vp[0], v23 = vp[1], v45 = vp[2];
        const float* rpr = rpw + a*49;
        #pragma unroll
        for (int p = 0; p < 8; p++) {
            u64 acc = fma2(q45[p], k45,
                       fma2(q23[p], k23,
                        fma2(q01[p], k01, 0ULL)));
            float lo, hi2; unpack2(acc, lo, hi2);
            int rj = min(max(lA0 - p, 0), 48);
            float lg = rpr[rj] + vadd[p] + lo + hi2;
            float pr = __expf(lg);
            sum[p] += pr;
            u64 pr2 = pack2(pr, pr);
            oa01[p] = fma2(pr2, v01, oa01[p]);
            oa23[p] = fma2(pr2, v23, oa23[p]);
            oa45[p] = fma2(pr2, v45, oa45[p]);
        }
    }

    #pragma unroll
    for (int p = 0; p < 8; p++) {
        float s = sum[p];
        float o0, o1, o2, o3, o4, o5;
        unpack2(oa01[p], o0, o1);
        unpack2(oa23[p], o2, o3);
        unpack2(oa45[p], o4, o5);
        #pragma unroll
        for (int off = 16; off > 0; off >>= 1) {
            s  += __shfl_xor_sync(0xffffffffu, s,  off);
            o0 += __shfl_xor_sync(0xffffffffu, o0, off);
            o1 += __shfl_xor_sync(0xffffffffu, o1, off);
            o2 += __shfl_xor_sync(0xffffffffu, o2, off);
            o3 += __shfl_xor_sync(0xffffffffu, o3, off);
            o4 += __shfl_xor_sync(0xffffffffu, o4, off);
            o5 += __shfl_xor_sync(0xffffffffu, o5, off);
        }
        if (lane == 0) {
            float inv = 1.0f / s;
            float* dst = g_ao + ((i*WW + j0 + p)*NUc + n*HDd);
            dst[0]=o0*inv; dst[1]=o1*inv; dst[2]=o2*inv;
            dst[3]=o3*inv; dst[4]=o4*inv; dst[5]=o5*inv;
        }
    }
}

// ---------------------------------------------------------------------------
// Projection epilogue: per i-row block (64 blocks, 512 threads).
// proj(24x24) on g_ao; then mode0: qkv(72x24) -> g_{q,k,v}1; mode1: head->out.
// ---------------------------------------------------------------------------
__global__ void __launch_bounds__(512)
proj_kernel(const float* __restrict__ pw,
            const float* __restrict__ pb,
            const float* __restrict__ qkv_w,
            const float* __restrict__ qkv_b,
            const float* __restrict__ ow,
            const float* __restrict__ ob,
            float* __restrict__ out,
            int mode)
{
    const int i = blockIdx.x;
    const int tid = threadIdx.x;
    __shared__ float aosh[WW*NUc];     // 2112
    __shared__ float posh[WW*NUc];     // 2112
    __shared__ float wpsh[NUc*NUc];    // 576
    __shared__ float w2sh[72*NUc];     // 1728 (qkv) or head weights
    __shared__ float bpsh[NUc], b2sh[72];

    for (int x = tid; x < WW*NUc/4; x += 512)
        ((float4*)aosh)[x] = ((const float4*)(g_ao + i*WW*NUc))[x];
    for (int x = tid; x < NUc*NUc; x += 512) wpsh[x] = pw[x];
    if (tid < NUc) bpsh[tid] = pb[tid];
    if (mode == 0) {
        for (int x = tid; x < 72*NUc; x += 512) w2sh[x] = qkv_w[x];
        if (tid < 72) b2sh[tid] = qkv_b[tid];
    } else {
        for (int x = tid; x < 5*NUc; x += 512) w2sh[x] = ow[x];
        if (tid < 5) b2sh[tid] = ob[tid];
    }
    __syncthreads();

    // projection: 88*24 = 2112 dots
    for (int idx = tid; idx < WW*NUc; idx += 512) {
        int px = idx / NUc, oc = idx % NUc;
        float acc = bpsh[oc];
        const float* xr = aosh + px*NUc;
        const float* wr = wpsh + oc*NUc;
        #pragma unroll
        for (int c = 0; c < NUc; c++) acc = fmaf(xr[c], wr[c], acc);
        posh[idx] = acc;
    }
    __syncthreads();

    if (mode == 0) {
        for (int idx = tid; idx < WW*72; idx += 512) {
            int px = idx / 72, oc = idx % 72;
            float acc = b2sh[oc];
            const float* xr = posh + px*NUc;
            const float* wr = w2sh + oc*NUc;
            #pragma unroll
            for (int c = 0; c < NUc; c++) acc = fmaf(xr[c], wr[c], acc);
            int e = oc / NUc, ch = oc % NUc;
            int gpx = i*WW + px;
            if      (e == 0) g_q1[gpx*NUc + ch] = acc * QSCALE;
            else if (e == 1) g_k1[gpx*NUc + ch] = acc;
            else             g_v1[gpx*NUc + ch] = acc;
        }
    } else {
        if (tid < WW*5) {
            int px = tid / 5, oc = tid % 5;
            float acc = b2sh[oc];
            const float* xr = posh + px*NUc;
            const float* wr = w2sh + oc*NUc;
            #pragma unroll
            for (int c = 0; c < NUc; c++) acc = fmaf(xr[c], wr[c], acc);
            out[(i*WW + px)*5 + oc] = acc;
        }
    }
}

// ---------------------------------------------------------------------------
extern "C" void kernel_launch(void* const* d_in, const int* in_sizes, int n_in,
                              void* d_out, int out_size)
{
    const float* features  = (const float*)d_in[0];
    const int*   condition = (const int*)  d_in[1];
    const float* mask      = (const float*)d_in[2];
    const float* emb       = (const float*)d_in[3];
    const float* wih0      = (const float*)d_in[4];
    const float* whh0      = (const float*)d_in[5];
    const float* bih0      = (const float*)d_in[6];
    const float* bhh0      = (const float*)d_in[7];
    const float* wih1      = (const float*)d_in[8];
    const float* whh1      = (const float*)d_in[9];
    const float* bih1      = (const float*)d_in[10];
    const float* bhh1      = (const float*)d_in[11];
    const float* qkv_w     = (const float*)d_in[12];
    const float* qkv_b     = (const float*)d_in[13];
    const float* rpb       = (const float*)d_in[14];
    const float* proj_w    = (const float*)d_in[15];
    const float* proj_b    = (const float*)d_in[16];
    const float* out_w     = (const float*)d_in[17];
    const float* out_b     = (const float*)d_in[18];
    float* out = (float*)d_out;

    float *pq0, *pk0, *pv0, *pq1, *pk1, *pv1;
    cudaGetSymbolAddress((void**)&pq0, g_q0);
    cudaGetSymbolAddress((void**)&pk0, g_k0);
    cudaGetSymbolAddress((void**)&pv0, g_v0);
    cudaGetSymbolAddress((void**)&pq1, g_q1);
    cudaGetSymbolAddress((void**)&pk1, g_k1);
    cudaGetSymbolAddress((void**)&pv1, g_v1);

    const int attn_smem =
        (2*UROWS*32*KVP + 2*RPROWS*49) * (int)sizeof(float);   // 111,328 B
    cudaFuncSetAttribute(natten_attn_kernel,
                         cudaFuncAttributeMaxDynamicSharedMemorySize, attn_smem);

    // 1) fused LSTM + QKV(layer1)
    lstm_kernel<<<WW, 768>>>(features, condition, mask, emb,
                             wih0, whh0, bih0, bhh0,
                             wih1, whh1, bih1, bhh1,
                             qkv_w, qkv_b);

    dim3 agrid(WW/8, TT/4, 2);   // 11 x 16 x 2 = 352 blocks

    // 2) NATTEN layer 1
    natten_attn_kernel<<<agrid, 256, attn_smem>>>(pq0, pk0, pv0, rpb);
    proj_kernel<<<TT, 512>>>(proj_w, proj_b, qkv_w, qkv_b, out_w, out_b,
                             nullptr, 0);

    // 3) NATTEN layer 2 + head
    natten_attn_kernel<<<agrid, 256, attn_smem>>>(pq1, pk1, pv1, rpb);
    proj_kernel<<<TT, 512>>>(proj_w, proj_b, qkv_w, qkv_b, out_w, out_b,
                             out, 1);
}

// round 13
// speedup vs baseline: 1.1563x; 1.1563x over previous
#include <cuda_runtime.h>
#include <cuda_bf16.h>

// Problem constants
#define TT   64
#define WW   88
#define HPc  48
#define CIN  53
#define HLc  12
#define G4   48
#define NHh  4
#define HDd  6
#define NUc  24
#define KK   25
#define NPX  (TT*WW)   // 5632
#define PITCH 26
#define UR2  26        // union rows for a 2-row tile
#define RP2  26

typedef unsigned long long u64;

// Scratch buffers (device globals)
__device__ float g_q0[NPX*NUc];
__device__ float g_k0[NPX*NUc];
__device__ float g_v0[NPX*NUc];
__device__ float g_q1[NPX*NUc];
__device__ float g_k1[NPX*NUc];
__device__ float g_v1[NPX*NUc];

#define QSCALE 0.4082482904638631f

__device__ __forceinline__ float sigf(float x) {
    return __fdividef(1.0f, 1.0f + __expf(-x));
}
__device__ __forceinline__ float tanh_fast(float x) {
    return fmaf(2.0f, __fdividef(1.0f, 1.0f + __expf(-2.0f*x)), -1.0f);
}

// packed f32x2 helpers
__device__ __forceinline__ u64 pack2(float lo, float hi) {
    u64 r; asm("mov.b64 %0, {%1,%2};" : "=l"(r) : "f"(lo), "f"(hi)); return r;
}
__device__ __forceinline__ void unpack2(u64 v, float& lo, float& hi) {
    asm("mov.b64 {%0,%1}, %2;" : "=f"(lo), "=f"(hi) : "l"(v));
}
__device__ __forceinline__ u64 fma2(u64 a, u64 b, u64 c) {
    u64 d; asm("fma.rn.f32x2 %0, %1, %2, %3;" : "=l"(d) : "l"(a), "l"(b), "l"(c));
    return d;
}

// ---------------------------------------------------------------------------
// Fused LSTM + QKV(layer1). Block per sequence (w), 768 threads.
// Recurrence gate dots use split accumulators (chain 12 -> 6 deep).
// ---------------------------------------------------------------------------
__global__ void __launch_bounds__(768)
lstm_kernel(const float* __restrict__ features,
            const int*   __restrict__ condition,
            const float* __restrict__ mask,
            const float* __restrict__ emb,
            const float* __restrict__ wih0, const float* __restrict__ whh0,
            const float* __restrict__ bih0, const float* __restrict__ bhh0,
            const float* __restrict__ wih1, const float* __restrict__ whh1,
            const float* __restrict__ bih1, const float* __restrict__ bhh1,
            const float* __restrict__ qkv_w,
            const float* __restrict__ qkv_b)
{
    const int w   = blockIdx.x;
    const int tid = threadIdx.x;

    __shared__ float xs  [TT][CIN];
    __shared__ float pre [TT][96];
    __shared__ float hbuf[TT][2*HLc];
    __shared__ float w0sh [96*CIN];
    __shared__ float wh0sh[96*HLc];
    __shared__ float w1sh [96*2*HLc];
    __shared__ float wh1sh[96*HLc];
    __shared__ float wqsh [72*NUc];
    __shared__ float b0sh[96], b1sh[96], bqsh[72];

    for (int idx = tid; idx < TT*CIN; idx += 768) {
        int t = idx / CIN, c = idx % CIN;
        float val;
        if (c < HPc)            val = features[(t*HPc + c)*WW + w];
        else if (c < HPc + 4)   val = emb[condition[t*WW + w]*4 + (c - HPc)];
        else                    val = mask[t*WW + w];
        xs[t][c] = val;
    }
    for (int x = tid; x < 96*CIN/4;   x += 768)
        ((float4*)w0sh)[x]  = ((const float4*)wih0)[x];
    for (int x = tid; x < 96*HLc/4;   x += 768)
        ((float4*)wh0sh)[x] = ((const float4*)whh0)[x];
    for (int x = tid; x < 96*2*HLc/4; x += 768)
        ((float4*)w1sh)[x]  = ((const float4*)wih1)[x];
    for (int x = tid; x < 96*HLc/4;   x += 768)
        ((float4*)wh1sh)[x] = ((const float4*)whh1)[x];
    for (int x = tid; x < 72*NUc/4;   x += 768)
        ((float4*)wqsh)[x]  = ((const float4*)qkv_w)[x];
    if (tid < 96) b0sh[tid] = bih0[tid] + bhh0[tid];
    if (tid < 96) b1sh[tid] = bih1[tid] + bhh1[tid];
    if (tid < 72) bqsh[tid] = qkv_b[tid];
    __syncthreads();

    {
        const int gate = tid % 96;
        const int tq   = tid / 96;
        float wr[CIN];
        #pragma unroll
        for (int c = 0; c < CIN; c++) wr[c] = w0sh[gate*CIN + c];
        const float b = b0sh[gate];
        for (int t = tq*8; t < tq*8 + 8; t++) {
            float a0 = b, a1 = 0.f, a2 = 0.f, a3 = 0.f;
            #pragma unroll
            for (int c = 0; c < 52; c += 4) {
                a0 = fmaf(xs[t][c+0], wr[c+0], a0);
                a1 = fmaf(xs[t][c+1], wr[c+1], a1);
                a2 = fmaf(xs[t][c+2], wr[c+2], a2);
                a3 = fmaf(xs[t][c+3], wr[c+3], a3);
            }
            a0 = fmaf(xs[t][52], wr[52], a0);
            pre[t][gate] = (a0 + a1) + (a2 + a3);
        }
    }
    __syncthreads();

    if (tid < 64) {
        const int dir = tid >> 5, u = tid & 31;
        float wi[HLc], wf[HLc], wg[HLc], wo[HLc];
        if (u < HLc) {
            #pragma unroll
            for (int c = 0; c < HLc; c++) {
                wi[c] = wh0sh[(dir*G4      + u)*HLc + c];
                wf[c] = wh0sh[(dir*G4 + 12 + u)*HLc + c];
                wg[c] = wh0sh[(dir*G4 + 24 + u)*HLc + c];
                wo[c] = wh0sh[(dir*G4 + 36 + u)*HLc + c];
            }
        } else {
            #pragma unroll
            for (int c = 0; c < HLc; c++) { wi[c]=wf[c]=wg[c]=wo[c]=0.f; }
        }
        float h = 0.f, cs = 0.f;
        for (int s = 0; s < TT; s++) {
            const int t = dir ? (TT - 1 - s) : s;
            float gi, gf, gg, go;
            if (u < HLc) {
                gi = pre[t][dir*G4      + u];
                gf = pre[t][dir*G4 + 12 + u];
                gg = pre[t][dir*G4 + 24 + u];
                go = pre[t][dir*G4 + 36 + u];
            } else { gi = gf = gg = go = 0.f; }
            float gi2=0.f, gf2=0.f, gg2=0.f, go2=0.f;
            #pragma unroll
            for (int c = 0; c < 6; c++) {
                float hc = __shfl_sync(0xffffffffu, h, c);
                gi = fmaf(hc, wi[c], gi);
                gf = fmaf(hc, wf[c], gf);
                gg = fmaf(hc, wg[c], gg);
                go = fmaf(hc, wo[c], go);
            }
            #pragma unroll
            for (int c = 6; c < HLc; c++) {
                float hc = __shfl_sync(0xffffffffu, h, c);
                gi2 = fmaf(hc, wi[c], gi2);
                gf2 = fmaf(hc, wf[c], gf2);
                gg2 = fmaf(hc, wg[c], gg2);
                go2 = fmaf(hc, wo[c], go2);
            }
            gi += gi2; gf += gf2; gg += gg2; go += go2;
            cs = sigf(gf)*cs + sigf(gi)*tanh_fast(gg);
            h  = sigf(go)*tanh_fast(cs);
            if (u < HLc) hbuf[t][dir*HLc + u] = h;
        }
    }
    __syncthreads();

    {
        const int gate = tid % 96;
        const int tq   = tid / 96;
        float wr[2*HLc];
        #pragma unroll
        for (int c = 0; c < 2*HLc; c++) wr[c] = w1sh[gate*2*HLc + c];
        const float b = b1sh[gate];
        for (int t = tq*8; t < tq*8 + 8; t++) {
            float a0 = b, a1 = 0.f, a2 = 0.f, a3 = 0.f;
            #pragma unroll
            for (int c = 0; c < 2*HLc; c += 4) {
                a0 = fmaf(hbuf[t][c+0], wr[c+0], a0);
                a1 = fmaf(hbuf[t][c+1], wr[c+1], a1);
                a2 = fmaf(hbuf[t][c+2], wr[c+2], a2);
                a3 = fmaf(hbuf[t][c+3], wr[c+3], a3);
            }
            pre[t][gate] = (a0 + a1) + (a2 + a3);
        }
    }
    __syncthreads();

    if (tid < 64) {
        const int dir = tid >> 5, u = tid & 31;
        float wi[HLc], wf[HLc], wg[HLc], wo[HLc];
        if (u < HLc) {
            #pragma unroll
            for (int c = 0; c < HLc; c++) {
                wi[c] = wh1sh[(dir*G4      + u)*HLc + c];
                wf[c] = wh1sh[(dir*G4 + 12 + u)*HLc + c];
                wg[c] = wh1sh[(dir*G4 + 24 + u)*HLc + c];
                wo[c] = wh1sh[(dir*G4 + 36 + u)*HLc + c];
            }
        } else {
            #pragma unroll
            for (int c = 0; c < HLc; c++) { wi[c]=wf[c]=wg[c]=wo[c]=0.f; }
        }
        float h = 0.f, cs = 0.f;
        for (int s = 0; s < TT; s++) {
            const int t = dir ? (TT - 1 - s) : s;
            float gi, gf, gg, go;
            if (u < HLc) {
                gi = pre[t][dir*G4      + u];
                gf = pre[t][dir*G4 + 12 + u];
                gg = pre[t][dir*G4 + 24 + u];
                go = pre[t][dir*G4 + 36 + u];
            } else { gi = gf = gg = go = 0.f; }
            float gi2=0.f, gf2=0.f, gg2=0.f, go2=0.f;
            #pragma unroll
            for (int c = 0; c < 6; c++) {
                float hc = __shfl_sync(0xffffffffu, h, c);
                gi = fmaf(hc, wi[c], gi);
                gf = fmaf(hc, wf[c], gf);
                gg = fmaf(hc, wg[c], gg);
                go = fmaf(hc, wo[c], go);
            }
            #pragma unroll
            for (int c = 6; c < HLc; c++) {
                float hc = __shfl_sync(0xffffffffu, h, c);
                gi2 = fmaf(hc, wi[c], gi2);
                gf2 = fmaf(hc, wf[c], gf2);
                gg2 = fmaf(hc, wg[c], gg2);
                go2 = fmaf(hc, wo[c], go2);
            }
            gi += gi2; gf += gf2; gg += gg2; go += go2;
            cs = sigf(gf)*cs + sigf(gi)*tanh_fast(gg);
            h  = sigf(go)*tanh_fast(cs);
            if (u < HLc) hbuf[t][dir*HLc + u] = h;
        }
    }
    __syncthreads();

    if (tid < 576) {
        const int oc = tid % 72;
        const int tq = tid / 72;
        float wr[NUc];
        #pragma unroll
        for (int c = 0; c < NUc; c++) wr[c] = wqsh[oc*NUc + c];
        const float b = bqsh[oc];
        const int e  = oc / NUc;
        const int ch = oc % NUc;
        const float scale = (e == 0) ? QSCALE : 1.0f;
        float* dst = (e == 0) ? g_q0 : (e == 1) ? g_k0 : g_v0;
        for (int t = tq*8; t < tq*8 + 8; t++) {
            float a0 = b, a1 = 0.f, a2 = 0.f, a3 = 0.f;
            #pragma unroll
            for (int c = 0; c < NUc; c += 4) {
                a0 = fmaf(hbuf[t][c+0], wr[c+0], a0);
                a1 = fmaf(hbuf[t][c+1], wr[c+1], a1);
                a2 = fmaf(hbuf[t][c+2], wr[c+2], a2);
                a3 = fmaf(hbuf[t][c+3], wr[c+3], a3);
            }
            dst[(t*WW + w)*NUc + ch] = ((a0 + a1) + (a2 + a3)) * scale;
        }
    }
}

// ---------------------------------------------------------------------------
// NATTEN-2D: 2x8 tile, 256 threads (8 warps = 4 heads x 2 rows), one task of
// 8 queries-in-registers per warp (R8 loop, no spills at 255 regs).
// 352 half-size blocks -> better wave packing than 176 full-size blocks.
// ---------------------------------------------------------------------------
__global__ void __launch_bounds__(256)
natten_kernel(const float* __restrict__ qsrc,
              const float* __restrict__ ksrc,
              const float* __restrict__ vsrc,
              const float* __restrict__ rpb,
              const float* __restrict__ pw,
              const float* __restrict__ pb,
              const float* __restrict__ qkv_w,
              const float* __restrict__ qkv_b,
              const float* __restrict__ ow,
              const float* __restrict__ ob,
              float* __restrict__ out,
              int mode)
{
    const int i0 = blockIdx.y * 2;
    const int j0 = blockIdx.x * 8;
    extern __shared__ float sm[];
    float* ks   = sm;                           // [26*32][PITCH]
    float* vs   = ks + UR2*32*PITCH;
    float* rpsh = vs + UR2*32*PITCH;            // [4][26][49]
    float* ao   = rpsh + 4*RP2*49;              // [16][24]
    float* po   = ao + 16*NUc;                  // [16][24]
    float* wsh  = po + 16*NUc;                  // [72*24]
    float* bsh  = wsh + 72*NUc;                 // [72]

    const int tid = threadIdx.x;

    const int si0 = min(max(i0     - 12, 0), TT - KK);
    const int si1 = min(max(i0 + 1 - 12, 0), TT - KK);
    const int nrows = si1 + KK - si0;                      // 25..26
    const int sj_min  = min(max(j0     - 12, 0), WW - KK);
    const int sj_last = min(max(j0 + 7 - 12, 0), WW - KK);
    const int ncols   = sj_last + KK - sj_min;             // <= 32
    const int rmin = si1 - (i0 + 1) + (KK - 1);

    if (mode == 0) {
        for (int x = tid; x < 72*NUc; x += 256) wsh[x] = qkv_w[x];
        if (tid < 72) bsh[tid] = qkv_b[tid];
    }

    for (int idx = tid; idx < 4*RP2*49; idx += 256) {
        int hn = idx / (RP2*49);
        int rem = idx - hn*(RP2*49);
        int rr = rem / 49, cc = rem - rr*49;
        rpsh[idx] = __ldg(rpb + hn*2401 + (rmin + rr)*49 + cc);
    }

    const int npx = nrows * 32;
    for (int spx = tid; spx < npx; spx += 256) {
        int a = spx >> 5, c = spx & 31;
        int cc = min(c, ncols - 1);
        int gpx = (si0 + a)*WW + (sj_min + cc);
        float* kdst = ks + (a*32 + c)*PITCH;
        float* vdst = vs + (a*32 + c)*PITCH;
        const float4* kp = (const float4*)(ksrc + gpx*NUc);
        const float4* vp = (const float4*)(vsrc + gpx*NUc);
        #pragma unroll
        for (int f = 0; f < 6; f++) {
            float4 kd = kp[f];
            *(float2*)(kdst + f*4)     = make_float2(kd.x, kd.y);
            *(float2*)(kdst + f*4 + 2) = make_float2(kd.z, kd.w);
        }
        #pragma unroll
        for (int f = 0; f < 6; f++) {
            float4 vd = vp[f];
            *(float2*)(vdst + f*4)     = make_float2(vd.x, vd.y);
            *(float2*)(vdst + f*4 + 2) = make_float2(vd.z, vd.w);
        }
    }
    __syncthreads();

    const int warp = tid >> 5, lane = tid & 31;
    const int n = warp & 3;             // head
    const int r = warp >> 2;            // row 0/1

    int   rjp[8];
    float vf [8];
    #pragma unroll
    for (int p = 0; p < 8; p++) {
        int sj = min(max(j0 + p - 12, 0), WW - KK);
        int cb = sj - sj_min;
        bool valid = ((unsigned)(lane - cb)) < 25u;
        int rj = (lane - cb) + (sj - (j0 + p) + (KK - 1));
        rjp[p] = min(max(rj, 0), 48);
        vf[p]  = valid ? 1.0f : 0.0f;
    }

    {
        const int i = i0 + r;
        const int sir = min(max(i - 12, 0), TT - KK);
        const int arow = sir - si0;                      // 0..1
        const int ra   = (sir - i + (KK - 1)) - rmin;    // 0..1
        const float* rpw = rpsh + n*(RP2*49) + ra*49;

        u64 q01[8], q23[8], q45[8];
        #pragma unroll
        for (int p = 0; p < 8; p++) {
            const u64* qp = (const u64*)(qsrc + ((i*WW + j0 + p)*NUc + n*HDd));
            q01[p] = qp[0]; q23[p] = qp[1]; q45[p] = qp[2];
        }

        float sum[8];
        u64 oa01[8], oa23[8], oa45[8];
        #pragma unroll
        for (int p = 0; p < 8; p++) {
            sum[p] = 0.f;
            oa01[p] = 0ULL; oa23[p] = 0ULL; oa45[p] = 0ULL;
        }

        #pragma unroll 1
        for (int a = 0; a < KK; a++) {
            const int base = ((arow + a)*32 + lane)*PITCH + n*HDd;
            const u64* kp = (const u64*)(ks + base);
            const u64* vp = (const u64*)(vs + base);
            u64 k01 = kp[0], k23 = kp[1], k45 = kp[2];
            u64 v01 = vp[0], v23 = vp[1], v45 = vp[2];
            const float* rpr = rpw + a*49;
            #pragma unroll
            for (int p = 0; p < 8; p++) {
                u64 acc = fma2(q45[p], k45,
                           fma2(q23[p], k23,
                            fma2(q01[p], k01, 0ULL)));
                float lo, hi; unpack2(acc, lo, hi);
                float lg = rpr[rjp[p]] + lo + hi;
                float pr = __expf(lg) * vf[p];
                sum[p] += pr;
                u64 pr2 = pack2(pr, pr);
                oa01[p] = fma2(pr2, v01, oa01[p]);
                oa23[p] = fma2(pr2, v23, oa23[p]);
                oa45[p] = fma2(pr2, v45, oa45[p]);
            }
        }

        #pragma unroll
        for (int p = 0; p < 8; p++) {
            float s = sum[p];
            float o0, o1, o2, o3, o4, o5;
            unpack2(oa01[p], o0, o1);
            unpack2(oa23[p], o2, o3);
            unpack2(oa45[p], o4, o5);
            #pragma unroll
            for (int off = 16; off > 0; off >>= 1) {
                s  += __shfl_xor_sync(0xffffffffu, s,  off);
                o0 += __shfl_xor_sync(0xffffffffu, o0, off);
                o1 += __shfl_xor_sync(0xffffffffu, o1, off);
                o2 += __shfl_xor_sync(0xffffffffu, o2, off);
                o3 += __shfl_xor_sync(0xffffffffu, o3, off);
                o4 += __shfl_xor_sync(0xffffffffu, o4, off);
                o5 += __shfl_xor_sync(0xffffffffu, o5, off);
            }
            if (lane == 0) {
                float inv = 1.0f / s;
                float* dst = ao + (r*8 + p)*NUc + n*HDd;
                dst[0]=o0*inv; dst[1]=o1*inv; dst[2]=o2*inv;
                dst[3]=o3*inv; dst[4]=o4*inv; dst[5]=o5*inv;
            }
        }
    }
    __syncthreads();

    // output projection (24x24) for 16 pixels
    for (int idx = tid; idx < 16*NUc; idx += 256) {
        int pp = idx / NUc, oc = idx % NUc;
        float acc = __ldg(pb + oc);
        const float* wrow = pw + oc*NUc;
        #pragma unroll
        for (int ic = 0; ic < NUc; ic++)
            acc = fmaf(ao[pp*NUc + ic], __ldg(wrow + ic), acc);
        po[pp*NUc + oc] = acc;
    }
    __syncthreads();

    if (mode == 0) {
        for (int idx = tid; idx < 16*72; idx += 256) {
            int pp = idx / 72, oc = idx % 72;
            float acc = bsh[oc];
            const float* wrow = wsh + oc*NUc;
            const float* xr = po + pp*NUc;
            #pragma unroll
            for (int c = 0; c < NUc; c++) acc = fmaf(xr[c], wrow[c], acc);
            int e = oc / NUc, ch = oc % NUc;
            int gpx = (i0 + (pp >> 3))*WW + j0 + (pp & 7);
            if      (e == 0) g_q1[gpx*NUc + ch] = acc * QSCALE;
            else if (e == 1) g_k1[gpx*NUc + ch] = acc;
            else             g_v1[gpx*NUc + ch] = acc;
        }
    } else {
        if (tid < 16*5) {
            int pp = tid / 5, rr = tid % 5;
            float acc = __ldg(ob + rr);
            const float* wrow = ow + rr*NUc;
            #pragma unroll
            for (int ic = 0; ic < NUc; ic++)
                acc = fmaf(po[pp*NUc + ic], __ldg(wrow + ic), acc);
            out[((i0 + (pp >> 3))*WW + j0 + (pp & 7))*5 + rr] = acc;
        }
    }
}

// ---------------------------------------------------------------------------
extern "C" void kernel_launch(void* const* d_in, const int* in_sizes, int n_in,
                              void* d_out, int out_size)
{
    const float* features  = (const float*)d_in[0];
    const int*   condition = (const int*)  d_in[1];
    const float* mask      = (const float*)d_in[2];
    const float* emb       = (const float*)d_in[3];
    const float* wih0      = (const float*)d_in[4];
    const float* whh0      = (const float*)d_in[5];
    const float* bih0      = (const float*)d_in[6];
    const float* bhh0      = (const float*)d_in[7];
    const float* wih1      = (const float*)d_in[8];
    const float* whh1      = (const float*)d_in[9];
    const float* bih1      = (const float*)d_in[10];
    const float* bhh1      = (const float*)d_in[11];
    const float* qkv_w     = (const float*)d_in[12];
    const float* qkv_b     = (const float*)d_in[13];
    const float* rpb       = (const float*)d_in[14];
    const float* proj_w    = (const float*)d_in[15];
    const float* proj_b    = (const float*)d_in[16];
    const float* out_w     = (const float*)d_in[17];
    const float* out_b     = (const float*)d_in[18];
    float* out = (float*)d_out;

    float *pq0, *pk0, *pv0, *pq1, *pk1, *pv1;
    cudaGetSymbolAddress((void**)&pq0, g_q0);
    cudaGetSymbolAddress((void**)&pk0, g_k0);
    cudaGetSymbolAddress((void**)&pv0, g_v0);
    cudaGetSymbolAddress((void**)&pq1, g_q1);
    cudaGetSymbolAddress((void**)&pk1, g_k1);
    cudaGetSymbolAddress((void**)&pv1, g_v1);

    const int natten_smem =
        (2*UR2*32*PITCH + 4*RP2*49 + 2*16*NUc + 72*NUc + 72)
        * (int)sizeof(float);   // ~204 KB
    cudaFuncSetAttribute(natten_kernel,
                         cudaFuncAttributeMaxDynamicSharedMemorySize, natten_smem);

    // 1) fused LSTM + QKV(layer1)
    lstm_kernel<<<WW, 768>>>(features, condition, mask, emb,
                             wih0, whh0, bih0, bhh0,
                             wih1, whh1, bih1, bhh1,
                             qkv_w, qkv_b);

    dim3 ngrid(WW/8, TT/2);   // 11 x 32 = 352 blocks

    // 2) NATTEN layer 1 (+ fused QKV for layer 2)
    natten_kernel<<<ngrid, 256, natten_smem>>>(pq0, pk0, pv0,
                                               rpb, proj_w, proj_b,
                                               qkv_w, qkv_b, out_w, out_b,
                                               nullptr, 0);

    // 3) NATTEN layer 2 (+ fused head) -> d_out
    natten_kernel<<<ngrid, 256, natten_smem>>>(pq1, pk1, pv1,
                                               rpb, proj_w, proj_b,
                                               qkv_w, qkv_b, out_w, out_b,
                                               out, 1);
}

// round 14
// speedup vs baseline: 1.3006x; 1.1248x over previous
#include <cuda_runtime.h>
#include <cuda_bf16.h>

// Problem constants
#define TT   64
#define WW   88
#define HPc  48
#define CIN  53
#define HLc  12
#define G4   48
#define NHh  4
#define HDd  6
#define NUc  24
#define KK   25
#define NPX  (TT*WW)   // 5632
#define PITCH 26
#define UROWS 28
#define RPROWS 28

// Scratch buffers (device globals)
__device__ float g_q0[NPX*NUc];
__device__ float g_k0[NPX*NUc];
__device__ float g_v0[NPX*NUc];
__device__ float g_q1[NPX*NUc];
__device__ float g_k1[NPX*NUc];
__device__ float g_v1[NPX*NUc];

#define QSCALE 0.4082482904638631f

__device__ __forceinline__ float sigf(float x) {
    return __fdividef(1.0f, 1.0f + __expf(-x));
}
__device__ __forceinline__ float tanh_fast(float x) {
    return fmaf(2.0f, __fdividef(1.0f, 1.0f + __expf(-2.0f*x)), -1.0f);
}

// ---------------------------------------------------------------------------
// Fused LSTM + QKV(layer1). Block per sequence (w), 768 threads. (R11/R9 exact)
// ---------------------------------------------------------------------------
__global__ void __launch_bounds__(768)
lstm_kernel(const float* __restrict__ features,
            const int*   __restrict__ condition,
            const float* __restrict__ mask,
            const float* __restrict__ emb,
            const float* __restrict__ wih0, const float* __restrict__ whh0,
            const float* __restrict__ bih0, const float* __restrict__ bhh0,
            const float* __restrict__ wih1, const float* __restrict__ whh1,
            const float* __restrict__ bih1, const float* __restrict__ bhh1,
            const float* __restrict__ qkv_w,
            const float* __restrict__ qkv_b)
{
    const int w   = blockIdx.x;
    const int tid = threadIdx.x;

    __shared__ float xs  [TT][CIN];
    __shared__ float pre [TT][96];
    __shared__ float hbuf[TT][2*HLc];
    __shared__ float w0sh [96*CIN];
    __shared__ float wh0sh[96*HLc];
    __shared__ float w1sh [96*2*HLc];
    __shared__ float wh1sh[96*HLc];
    __shared__ float wqsh [72*NUc];
    __shared__ float b0sh[96], b1sh[96], bqsh[72];

    for (int idx = tid; idx < TT*CIN; idx += 768) {
        int t = idx / CIN, c = idx % CIN;
        float val;
        if (c < HPc)            val = features[(t*HPc + c)*WW + w];
        else if (c < HPc + 4)   val = emb[condition[t*WW + w]*4 + (c - HPc)];
        else                    val = mask[t*WW + w];
        xs[t][c] = val;
    }
    for (int x = tid; x < 96*CIN/4;   x += 768)
        ((float4*)w0sh)[x]  = ((const float4*)wih0)[x];
    for (int x = tid; x < 96*HLc/4;   x += 768)
        ((float4*)wh0sh)[x] = ((const float4*)whh0)[x];
    for (int x = tid; x < 96*2*HLc/4; x += 768)
        ((float4*)w1sh)[x]  = ((const float4*)wih1)[x];
    for (int x = tid; x < 96*HLc/4;   x += 768)
        ((float4*)wh1sh)[x] = ((const float4*)whh1)[x];
    for (int x = tid; x < 72*NUc/4;   x += 768)
        ((float4*)wqsh)[x]  = ((const float4*)qkv_w)[x];
    if (tid < 96) b0sh[tid] = bih0[tid] + bhh0[tid];
    if (tid < 96) b1sh[tid] = bih1[tid] + bhh1[tid];
    if (tid < 72) bqsh[tid] = qkv_b[tid];
    __syncthreads();

    {
        const int gate = tid % 96;
        const int tq   = tid / 96;
        float wr[CIN];
        #pragma unroll
        for (int c = 0; c < CIN; c++) wr[c] = w0sh[gate*CIN + c];
        const float b = b0sh[gate];
        for (int t = tq*8; t < tq*8 + 8; t++) {
            float a0 = b, a1 = 0.f, a2 = 0.f, a3 = 0.f;
            #pragma unroll
            for (int c = 0; c < 52; c += 4) {
                a0 = fmaf(xs[t][c+0], wr[c+0], a0);
                a1 = fmaf(xs[t][c+1], wr[c+1], a1);
                a2 = fmaf(xs[t][c+2], wr[c+2], a2);
                a3 = fmaf(xs[t][c+3], wr[c+3], a3);
            }
            a0 = fmaf(xs[t][52], wr[52], a0);
            pre[t][gate] = (a0 + a1) + (a2 + a3);
        }
    }
    __syncthreads();

    if (tid < 64) {
        const int dir = tid >> 5, u = tid & 31;
        float wi[HLc], wf[HLc], wg[HLc], wo[HLc];
        if (u < HLc) {
            #pragma unroll
            for (int c = 0; c < HLc; c++) {
                wi[c] = wh0sh[(dir*G4      + u)*HLc + c];
                wf[c] = wh0sh[(dir*G4 + 12 + u)*HLc + c];
                wg[c] = wh0sh[(dir*G4 + 24 + u)*HLc + c];
                wo[c] = wh0sh[(dir*G4 + 36 + u)*HLc + c];
            }
        } else {
            #pragma unroll
            for (int c = 0; c < HLc; c++) { wi[c]=wf[c]=wg[c]=wo[c]=0.f; }
        }
        float h = 0.f, cs = 0.f;
        for (int s = 0; s < TT; s++) {
            const int t = dir ? (TT - 1 - s) : s;
            float gi, gf, gg, go;
            if (u < HLc) {
                gi = pre[t][dir*G4      + u];
                gf = pre[t][dir*G4 + 12 + u];
                gg = pre[t][dir*G4 + 24 + u];
                go = pre[t][dir*G4 + 36 + u];
            } else { gi = gf = gg = go = 0.f; }
            #pragma unroll
            for (int c = 0; c < HLc; c++) {
                float hc = __shfl_sync(0xffffffffu, h, c);
                gi = fmaf(hc, wi[c], gi);
                gf = fmaf(hc, wf[c], gf);
                gg = fmaf(hc, wg[c], gg);
                go = fmaf(hc, wo[c], go);
            }
            cs = sigf(gf)*cs + sigf(gi)*tanh_fast(gg);
            h  = sigf(go)*tanh_fast(cs);
            if (u < HLc) hbuf[t][dir*HLc + u] = h;
        }
    }
    __syncthreads();

    {
        const int gate = tid % 96;
        const int tq   = tid / 96;
        float wr[2*HLc];
        #pragma unroll
        for (int c = 0; c < 2*HLc; c++) wr[c] = w1sh[gate*2*HLc + c];
        const float b = b1sh[gate];
        for (int t = tq*8; t < tq*8 + 8; t++) {
            float a0 = b, a1 = 0.f, a2 = 0.f, a3 = 0.f;
            #pragma unroll
            for (int c = 0; c < 2*HLc; c += 4) {
                a0 = fmaf(hbuf[t][c+0], wr[c+0], a0);
                a1 = fmaf(hbuf[t][c+1], wr[c+1], a1);
                a2 = fmaf(hbuf[t][c+2], wr[c+2], a2);
                a3 = fmaf(hbuf[t][c+3], wr[c+3], a3);
            }
            pre[t][gate] = (a0 + a1) + (a2 + a3);
        }
    }
    __syncthreads();

    if (tid < 64) {
        const int dir = tid >> 5, u = tid & 31;
        float wi[HLc], wf[HLc], wg[HLc], wo[HLc];
        if (u < HLc) {
            #pragma unroll
            for (int c = 0; c < HLc; c++) {
                wi[c] = wh1sh[(dir*G4      + u)*HLc + c];
                wf[c] = wh1sh[(dir*G4 + 12 + u)*HLc + c];
                wg[c] = wh1sh[(dir*G4 + 24 + u)*HLc + c];
                wo[c] = wh1sh[(dir*G4 + 36 + u)*HLc + c];
            }
        } else {
            #pragma unroll
            for (int c = 0; c < HLc; c++) { wi[c]=wf[c]=wg[c]=wo[c]=0.f; }
        }
        float h = 0.f, cs = 0.f;
        for (int s = 0; s < TT; s++) {
            const int t = dir ? (TT - 1 - s) : s;
            float gi, gf, gg, go;
            if (u < HLc) {
                gi = pre[t][dir*G4      + u];
                gf = pre[t][dir*G4 + 12 + u];
                gg = pre[t][dir*G4 + 24 + u];
                go = pre[t][dir*G4 + 36 + u];
            } else { gi = gf = gg = go = 0.f; }
            #pragma unroll
            for (int c = 0; c < HLc; c++) {
                float hc = __shfl_sync(0xffffffffu, h, c);
                gi = fmaf(hc, wi[c], gi);
                gf = fmaf(hc, wf[c], gf);
                gg = fmaf(hc, wg[c], gg);
                go = fmaf(hc, wo[c], go);
            }
            cs = sigf(gf)*cs + sigf(gi)*tanh_fast(gg);
            h  = sigf(go)*tanh_fast(cs);
            if (u < HLc) hbuf[t][dir*HLc + u] = h;
        }
    }
    __syncthreads();

    if (tid < 576) {
        const int oc = tid % 72;
        const int tq = tid / 72;
        float wr[NUc];
        #pragma unroll
        for (int c = 0; c < NUc; c++) wr[c] = wqsh[oc*NUc + c];
        const float b = bqsh[oc];
        const int e  = oc / NUc;
        const int ch = oc % NUc;
        const float scale = (e == 0) ? QSCALE : 1.0f;
        float* dst = (e == 0) ? g_q0 : (e == 1) ? g_k0 : g_v0;
        for (int t = tq*8; t < tq*8 + 8; t++) {
            float a0 = b, a1 = 0.f, a2 = 0.f, a3 = 0.f;
            #pragma unroll
            for (int c = 0; c < NUc; c += 4) {
                a0 = fmaf(hbuf[t][c+0], wr[c+0], a0);
                a1 = fmaf(hbuf[t][c+1], wr[c+1], a1);
                a2 = fmaf(hbuf[t][c+2], wr[c+2], a2);
                a3 = fmaf(hbuf[t][c+3], wr[c+3], a3);
            }
            dst[(t*WW + w)*NUc + ch] = ((a0 + a1) + (a2 + a3)) * scale;
        }
    }
}

// ---------------------------------------------------------------------------
// NATTEN-2D (R8 exact): 4x8 tile, 256 threads (8 warps), warp=(head,row-pair),
// 2 tasks x 8 queries-in-registers. Unshifted softmax. Plain fmaf.
// ---------------------------------------------------------------------------
__global__ void __launch_bounds__(256)
natten_kernel(const float* __restrict__ qsrc,
              const float* __restrict__ ksrc,
              const float* __restrict__ vsrc,
              const float* __restrict__ rpb,
              const float* __restrict__ pw,
              const float* __restrict__ pb,
              const float* __restrict__ qkv_w,
              const float* __restrict__ qkv_b,
              const float* __restrict__ ow,
              const float* __restrict__ ob,
              float* __restrict__ out,
              int mode)
{
    const int i0 = blockIdx.y * 4;
    const int j0 = blockIdx.x * 8;
    extern __shared__ float sm[];
    float* ks   = sm;                           // [28*32][PITCH]
    float* vs   = ks + UROWS*32*PITCH;
    float* rpsh = vs + UROWS*32*PITCH;          // [4][28][49]
    float* ao   = rpsh + 4*RPROWS*49;           // [32][24]
    float* po   = ao + 32*NUc;                  // [32][24]
    float* wsh  = po + 32*NUc;                  // [72*24]
    float* bsh  = wsh + 72*NUc;                 // [72]

    const int tid = threadIdx.x;

    const int si0 = min(max(i0     - 12, 0), TT - KK);
    const int si3 = min(max(i0 + 3 - 12, 0), TT - KK);
    const int nrows = si3 + KK - si0;                      // 25..28
    const int sj_min  = min(max(j0     - 12, 0), WW - KK);
    const int sj_last = min(max(j0 + 7 - 12, 0), WW - KK);
    const int ncols   = sj_last + KK - sj_min;             // <= 32
    const int rmin = si3 - (i0 + 3) + (KK - 1);

    if (mode == 0) {
        for (int x = tid; x < 72*NUc; x += 256) wsh[x] = qkv_w[x];
        if (tid < 72) bsh[tid] = qkv_b[tid];
    }

    for (int idx = tid; idx < 4*RPROWS*49; idx += 256) {
        int hn = idx / (RPROWS*49);
        int rem = idx - hn*(RPROWS*49);
        int rr = rem / 49, cc = rem - rr*49;
        rpsh[idx] = __ldg(rpb + hn*2401 + (rmin + rr)*49 + cc);
    }

    const int npx = nrows * 32;
    for (int spx = tid; spx < npx; spx += 256) {
        int a = spx >> 5, c = spx & 31;
        int cc = min(c, ncols - 1);
        int gpx = (si0 + a)*WW + (sj_min + cc);
        float* kdst = ks + (a*32 + c)*PITCH;
        float* vdst = vs + (a*32 + c)*PITCH;
        const float4* kp = (const float4*)(ksrc + gpx*NUc);
        const float4* vp = (const float4*)(vsrc + gpx*NUc);
        #pragma unroll
        for (int f = 0; f < 6; f++) {
            float4 kd = kp[f];
            *(float2*)(kdst + f*4)     = make_float2(kd.x, kd.y);
            *(float2*)(kdst + f*4 + 2) = make_float2(kd.z, kd.w);
        }
        #pragma unroll
        for (int f = 0; f < 6; f++) {
            float4 vd = vp[f];
            *(float2*)(vdst + f*4)     = make_float2(vd.x, vd.y);
            *(float2*)(vdst + f*4 + 2) = make_float2(vd.z, vd.w);
        }
    }
    __syncthreads();

    const int warp = tid >> 5, lane = tid & 31;
    const int n  = warp & 3;            // head
    const int rp = warp >> 2;           // row-pair 0/1

    int   rjp[8];
    float vf [8];
    #pragma unroll
    for (int p = 0; p < 8; p++) {
        int sj = min(max(j0 + p - 12, 0), WW - KK);
        int cb = sj - sj_min;
        bool valid = ((unsigned)(lane - cb)) < 25u;
        int rj = (lane - cb) + (sj - (j0 + p) + (KK - 1));
        rjp[p] = min(max(rj, 0), 48);
        vf[p]  = valid ? 1.0f : 0.0f;
    }

    for (int tr = 0; tr < 2; tr++) {
        const int r = rp*2 + tr;
        const int i = i0 + r;
        const int sir = min(max(i - 12, 0), TT - KK);
        const int arow = sir - si0;
        const int ra   = (sir - i + (KK - 1)) - rmin;
        const float* rpw = rpsh + n*(RPROWS*49) + ra*49;

        float qv[48];
        #pragma unroll
        for (int p = 0; p < 8; p++) {
            const float2* qp = (const float2*)(qsrc + ((i*WW + j0 + p)*NUc + n*HDd));
            float2 a0 = qp[0], a1 = qp[1], a2 = qp[2];
            qv[p*6+0]=a0.x; qv[p*6+1]=a0.y;
            qv[p*6+2]=a1.x; qv[p*6+3]=a1.y;
            qv[p*6+4]=a2.x; qv[p*6+5]=a2.y;
        }

        float sum[8];
        float oa[48];
        #pragma unroll
        for (int p = 0; p < 8; p++) sum[p] = 0.f;
        #pragma unroll
        for (int x = 0; x < 48; x++) oa[x] = 0.f;

        #pragma unroll 1
        for (int a = 0; a < KK; a++) {
            const int base = ((arow + a)*32 + lane)*PITCH + n*HDd;
            const float* kp = ks + base;
            const float* vp = vs + base;
            float2 k01 = *(const float2*)(kp);
            float2 k23 = *(const float2*)(kp + 2);
            float2 k45 = *(const float2*)(kp + 4);
            float2 v01 = *(const float2*)(vp);
            float2 v23 = *(const float2*)(vp + 2);
            float2 v45 = *(const float2*)(vp + 4);
            const float* rpr = rpw + a*49;
            #pragma unroll
            for (int p = 0; p < 8; p++) {
                float lg = rpr[rjp[p]];
                lg = fmaf(qv[p*6+0], k01.x, lg);
                lg = fmaf(qv[p*6+1], k01.y, lg);
                lg = fmaf(qv[p*6+2], k23.x, lg);
                lg = fmaf(qv[p*6+3], k23.y, lg);
                lg = fmaf(qv[p*6+4], k45.x, lg);
                lg = fmaf(qv[p*6+5], k45.y, lg);
                float pr = __expf(lg) * vf[p];
                sum[p] += pr;
                oa[p*6+0] = fmaf(pr, v01.x, oa[p*6+0]);
                oa[p*6+1] = fmaf(pr, v01.y, oa[p*6+1]);
                oa[p*6+2] = fmaf(pr, v23.x, oa[p*6+2]);
                oa[p*6+3] = fmaf(pr, v23.y, oa[p*6+3]);
                oa[p*6+4] = fmaf(pr, v45.x, oa[p*6+4]);
                oa[p*6+5] = fmaf(pr, v45.y, oa[p*6+5]);
            }
        }

        #pragma unroll
        for (int p = 0; p < 8; p++) {
            float s  = sum[p];
            float o0 = oa[p*6+0], o1 = oa[p*6+1], o2 = oa[p*6+2];
            float o3 = oa[p*6+3], o4 = oa[p*6+4], o5 = oa[p*6+5];
            #pragma unroll
            for (int off = 16; off > 0; off >>= 1) {
                s  += __shfl_xor_sync(0xffffffffu, s,  off);
                o0 += __shfl_xor_sync(0xffffffffu, o0, off);
                o1 += __shfl_xor_sync(0xffffffffu, o1, off);
                o2 += __shfl_xor_sync(0xffffffffu, o2, off);
                o3 += __shfl_xor_sync(0xffffffffu, o3, off);
                o4 += __shfl_xor_sync(0xffffffffu, o4, off);
                o5 += __shfl_xor_sync(0xffffffffu, o5, off);
            }
            if (lane == 0) {
                float inv = 1.0f / s;
                float* dst = ao + (r*8 + p)*NUc + n*HDd;
                dst[0]=o0*inv; dst[1]=o1*inv; dst[2]=o2*inv;
                dst[3]=o3*inv; dst[4]=o4*inv; dst[5]=o5*inv;
            }
        }
    }
    __syncthreads();

    // output projection (24x24) for 32 pixels
    for (int idx = tid; idx < 32*NUc; idx += 256) {
        int pp = idx / NUc, oc = idx % NUc;
        float acc = __ldg(pb + oc);
        const float* wrow = pw + oc*NUc;
        #pragma unroll
        for (int ic = 0; ic < NUc; ic++)
            acc = fmaf(ao[pp*NUc + ic], __ldg(wrow + ic), acc);
        po[pp*NUc + oc] = acc;
    }
    __syncthreads();

    if (mode == 0) {
        for (int idx = tid; idx < 32*72; idx += 256) {
            int pp = idx / 72, oc = idx % 72;
            float acc = bsh[oc];
            const float* wrow = wsh + oc*NUc;
            const float* xr = po + pp*NUc;
            #pragma unroll
            for (int c = 0; c < NUc; c++) acc = fmaf(xr[c], wrow[c], acc);
            int e = oc / NUc, ch = oc % NUc;
            int gpx = (i0 + (pp >> 3))*WW + j0 + (pp & 7);
            if      (e == 0) g_q1[gpx*NUc + ch] = acc * QSCALE;
            else if (e == 1) g_k1[gpx*NUc + ch] = acc;
            else             g_v1[gpx*NUc + ch] = acc;
        }
    } else {
        if (tid < 32*5) {
            int pp = tid / 5, rr = tid % 5;
            float acc = __ldg(ob + rr);
            const float* wrow = ow + rr*NUc;
            #pragma unroll
            for (int ic = 0; ic < NUc; ic++)
                acc = fmaf(po[pp*NUc + ic], __ldg(wrow + ic), acc);
            out[((i0 + (pp >> 3))*WW + j0 + (pp & 7))*5 + rr] = acc;
        }
    }
}

// ---------------------------------------------------------------------------
extern "C" void kernel_launch(void* const* d_in, const int* in_sizes, int n_in,
                              void* d_out, int out_size)
{
    const float* features  = (const float*)d_in[0];
    const int*   condition = (const int*)  d_in[1];
    const float* mask      = (const float*)d_in[2];
    const float* emb       = (const float*)d_in[3];
    const float* wih0      = (const float*)d_in[4];
    const float* whh0      = (const float*)d_in[5];
    const float* bih0      = (const float*)d_in[6];
    const float* bhh0      = (const float*)d_in[7];
    const float* wih1      = (const float*)d_in[8];
    const float* whh1      = (const float*)d_in[9];
    const float* bih1      = (const float*)d_in[10];
    const float* bhh1      = (const float*)d_in[11];
    const float* qkv_w     = (const float*)d_in[12];
    const float* qkv_b     = (const float*)d_in[13];
    const float* rpb       = (const float*)d_in[14];
    const float* proj_w    = (const float*)d_in[15];
    const float* proj_b    = (const float*)d_in[16];
    const float* out_w     = (const float*)d_in[17];
    const float* out_b     = (const float*)d_in[18];
    float* out = (float*)d_out;

    float *pq0, *pk0, *pv0, *pq1, *pk1, *pv1;
    cudaGetSymbolAddress((void**)&pq0, g_q0);
    cudaGetSymbolAddress((void**)&pk0, g_k0);
    cudaGetSymbolAddress((void**)&pv0, g_v0);
    cudaGetSymbolAddress((void**)&pq1, g_q1);
    cudaGetSymbolAddress((void**)&pk1, g_k1);
    cudaGetSymbolAddress((void**)&pv1, g_v1);

    const int natten_smem =
        (2*UROWS*32*PITCH + 4*RPROWS*49 + 2*32*NUc + 72*NUc + 72)
        * (int)sizeof(float);
    cudaFuncSetAttribute(natten_kernel,
                         cudaFuncAttributeMaxDynamicSharedMemorySize, natten_smem);

    // 1) fused LSTM + QKV(layer1)
    lstm_kernel<<<WW, 768>>>(features, condition, mask, emb,
                             wih0, whh0, bih0, bhh0,
                             wih1, whh1, bih1, bhh1,
                             qkv_w, qkv_b);

    dim3 ngrid(WW/8, TT/4);   // 11 x 16 = 176 blocks

    // 2) NATTEN layer 1 (+ fused QKV for layer 2)
    natten_kernel<<<ngrid, 256, natten_smem>>>(pq0, pk0, pv0,
                                               rpb, proj_w, proj_b,
                                               qkv_w, qkv_b, out_w, out_b,
                                               nullptr, 0);

    // 3) NATTEN layer 2 (+ fused head) -> d_out
    natten_kernel<<<ngrid, 256, natten_smem>>>(pq1, pk1, pv1,
                                               rpb, proj_w, proj_b,
                                               qkv_w, qkv_b, out_w, out_b,
                                               out, 1);
}

// round 15
// speedup vs baseline: 1.3408x; 1.0309x over previous
#include <cuda_runtime.h>
#include <cuda_bf16.h>

// Problem constants
#define TT   64
#define WW   88
#define HPc  48
#define CIN  53
#define HLc  12
#define G4   48
#define NHh  4
#define HDd  6
#define NUc  24
#define KK   25
#define NPX  (TT*WW)   // 5632
#define PITCH 26
#define UROWS 28
#define RPROWS 28

// Scratch buffers (device globals)
__device__ float g_q0[NPX*NUc];
__device__ float g_k0[NPX*NUc];
__device__ float g_v0[NPX*NUc];
__device__ float g_q1[NPX*NUc];
__device__ float g_k1[NPX*NUc];
__device__ float g_v1[NPX*NUc];

#define QSCALE 0.4082482904638631f

__device__ __forceinline__ float sigf(float x) {
    return __fdividef(1.0f, 1.0f + __expf(-x));
}
__device__ __forceinline__ float tanh_fast(float x) {
    return fmaf(2.0f, __fdividef(1.0f, 1.0f + __expf(-2.0f*x)), -1.0f);
}

// ---------------------------------------------------------------------------
// Fused LSTM + QKV(layer1). Block per sequence (w), 768 threads. (R14 exact)
// ---------------------------------------------------------------------------
__global__ void __launch_bounds__(768)
lstm_kernel(const float* __restrict__ features,
            const int*   __restrict__ condition,
            const float* __restrict__ mask,
            const float* __restrict__ emb,
            const float* __restrict__ wih0, const float* __restrict__ whh0,
            const float* __restrict__ bih0, const float* __restrict__ bhh0,
            const float* __restrict__ wih1, const float* __restrict__ whh1,
            const float* __restrict__ bih1, const float* __restrict__ bhh1,
            const float* __restrict__ qkv_w,
            const float* __restrict__ qkv_b)
{
    const int w   = blockIdx.x;
    const int tid = threadIdx.x;

    __shared__ float xs  [TT][CIN];
    __shared__ float pre [TT][96];
    __shared__ float hbuf[TT][2*HLc];
    __shared__ float w0sh [96*CIN];
    __shared__ float wh0sh[96*HLc];
    __shared__ float w1sh [96*2*HLc];
    __shared__ float wh1sh[96*HLc];
    __shared__ float wqsh [72*NUc];
    __shared__ float b0sh[96], b1sh[96], bqsh[72];

    for (int idx = tid; idx < TT*CIN; idx += 768) {
        int t = idx / CIN, c = idx % CIN;
        float val;
        if (c < HPc)            val = features[(t*HPc + c)*WW + w];
        else if (c < HPc + 4)   val = emb[condition[t*WW + w]*4 + (c - HPc)];
        else                    val = mask[t*WW + w];
        xs[t][c] = val;
    }
    for (int x = tid; x < 96*CIN/4;   x += 768)
        ((float4*)w0sh)[x]  = ((const float4*)wih0)[x];
    for (int x = tid; x < 96*HLc/4;   x += 768)
        ((float4*)wh0sh)[x] = ((const float4*)whh0)[x];
    for (int x = tid; x < 96*2*HLc/4; x += 768)
        ((float4*)w1sh)[x]  = ((const float4*)wih1)[x];
    for (int x = tid; x < 96*HLc/4;   x += 768)
        ((float4*)wh1sh)[x] = ((const float4*)whh1)[x];
    for (int x = tid; x < 72*NUc/4;   x += 768)
        ((float4*)wqsh)[x]  = ((const float4*)qkv_w)[x];
    if (tid < 96) b0sh[tid] = bih0[tid] + bhh0[tid];
    if (tid < 96) b1sh[tid] = bih1[tid] + bhh1[tid];
    if (tid < 72) bqsh[tid] = qkv_b[tid];
    __syncthreads();

    {
        const int gate = tid % 96;
        const int tq   = tid / 96;
        float wr[CIN];
        #pragma unroll
        for (int c = 0; c < CIN; c++) wr[c] = w0sh[gate*CIN + c];
        const float b = b0sh[gate];
        for (int t = tq*8; t < tq*8 + 8; t++) {
            float a0 = b, a1 = 0.f, a2 = 0.f, a3 = 0.f;
            #pragma unroll
            for (int c = 0; c < 52; c += 4) {
                a0 = fmaf(xs[t][c+0], wr[c+0], a0);
                a1 = fmaf(xs[t][c+1], wr[c+1], a1);
                a2 = fmaf(xs[t][c+2], wr[c+2], a2);
                a3 = fmaf(xs[t][c+3], wr[c+3], a3);
            }
            a0 = fmaf(xs[t][52], wr[52], a0);
            pre[t][gate] = (a0 + a1) + (a2 + a3);
        }
    }
    __syncthreads();

    if (tid < 64) {
        const int dir = tid >> 5, u = tid & 31;
        float wi[HLc], wf[HLc], wg[HLc], wo[HLc];
        if (u < HLc) {
            #pragma unroll
            for (int c = 0; c < HLc; c++) {
                wi[c] = wh0sh[(dir*G4      + u)*HLc + c];
                wf[c] = wh0sh[(dir*G4 + 12 + u)*HLc + c];
                wg[c] = wh0sh[(dir*G4 + 24 + u)*HLc + c];
                wo[c] = wh0sh[(dir*G4 + 36 + u)*HLc + c];
            }
        } else {
            #pragma unroll
            for (int c = 0; c < HLc; c++) { wi[c]=wf[c]=wg[c]=wo[c]=0.f; }
        }
        float h = 0.f, cs = 0.f;
        for (int s = 0; s < TT; s++) {
            const int t = dir ? (TT - 1 - s) : s;
            float gi, gf, gg, go;
            if (u < HLc) {
                gi = pre[t][dir*G4      + u];
                gf = pre[t][dir*G4 + 12 + u];
                gg = pre[t][dir*G4 + 24 + u];
                go = pre[t][dir*G4 + 36 + u];
            } else { gi = gf = gg = go = 0.f; }
            #pragma unroll
            for (int c = 0; c < HLc; c++) {
                float hc = __shfl_sync(0xffffffffu, h, c);
                gi = fmaf(hc, wi[c], gi);
                gf = fmaf(hc, wf[c], gf);
                gg = fmaf(hc, wg[c], gg);
                go = fmaf(hc, wo[c], go);
            }
            cs = sigf(gf)*cs + sigf(gi)*tanh_fast(gg);
            h  = sigf(go)*tanh_fast(cs);
            if (u < HLc) hbuf[t][dir*HLc + u] = h;
        }
    }
    __syncthreads();

    {
        const int gate = tid % 96;
        const int tq   = tid / 96;
        float wr[2*HLc];
        #pragma unroll
        for (int c = 0; c < 2*HLc; c++) wr[c] = w1sh[gate*2*HLc + c];
        const float b = b1sh[gate];
        for (int t = tq*8; t < tq*8 + 8; t++) {
            float a0 = b, a1 = 0.f, a2 = 0.f, a3 = 0.f;
            #pragma unroll
            for (int c = 0; c < 2*HLc; c += 4) {
                a0 = fmaf(hbuf[t][c+0], wr[c+0], a0);
                a1 = fmaf(hbuf[t][c+1], wr[c+1], a1);
                a2 = fmaf(hbuf[t][c+2], wr[c+2], a2);
                a3 = fmaf(hbuf[t][c+3], wr[c+3], a3);
            }
            pre[t][gate] = (a0 + a1) + (a2 + a3);
        }
    }
    __syncthreads();

    if (tid < 64) {
        const int dir = tid >> 5, u = tid & 31;
        float wi[HLc], wf[HLc], wg[HLc], wo[HLc];
        if (u < HLc) {
            #pragma unroll
            for (int c = 0; c < HLc; c++) {
                wi[c] = wh1sh[(dir*G4      + u)*HLc + c];
                wf[c] = wh1sh[(dir*G4 + 12 + u)*HLc + c];
                wg[c] = wh1sh[(dir*G4 + 24 + u)*HLc + c];
                wo[c] = wh1sh[(dir*G4 + 36 + u)*HLc + c];
            }
        } else {
            #pragma unroll
            for (int c = 0; c < HLc; c++) { wi[c]=wf[c]=wg[c]=wo[c]=0.f; }
        }
        float h = 0.f, cs = 0.f;
        for (int s = 0; s < TT; s++) {
            const int t = dir ? (TT - 1 - s) : s;
            float gi, gf, gg, go;
            if (u < HLc) {
                gi = pre[t][dir*G4      + u];
                gf = pre[t][dir*G4 + 12 + u];
                gg = pre[t][dir*G4 + 24 + u];
                go = pre[t][dir*G4 + 36 + u];
            } else { gi = gf = gg = go = 0.f; }
            #pragma unroll
            for (int c = 0; c < HLc; c++) {
                float hc = __shfl_sync(0xffffffffu, h, c);
                gi = fmaf(hc, wi[c], gi);
                gf = fmaf(hc, wf[c], gf);
                gg = fmaf(hc, wg[c], gg);
                go = fmaf(hc, wo[c], go);
            }
            cs = sigf(gf)*cs + sigf(gi)*tanh_fast(gg);
            h  = sigf(go)*tanh_fast(cs);
            if (u < HLc) hbuf[t][dir*HLc + u] = h;
        }
    }
    __syncthreads();

    if (tid < 576) {
        const int oc = tid % 72;
        const int tq = tid / 72;
        float wr[NUc];
        #pragma unroll
        for (int c = 0; c < NUc; c++) wr[c] = wqsh[oc*NUc + c];
        const float b = bqsh[oc];
        const int e  = oc / NUc;
        const int ch = oc % NUc;
        const float scale = (e == 0) ? QSCALE : 1.0f;
        float* dst = (e == 0) ? g_q0 : (e == 1) ? g_k0 : g_v0;
        for (int t = tq*8; t < tq*8 + 8; t++) {
            float a0 = b, a1 = 0.f, a2 = 0.f, a3 = 0.f;
            #pragma unroll
            for (int c = 0; c < NUc; c += 4) {
                a0 = fmaf(hbuf[t][c+0], wr[c+0], a0);
                a1 = fmaf(hbuf[t][c+1], wr[c+1], a1);
                a2 = fmaf(hbuf[t][c+2], wr[c+2], a2);
                a3 = fmaf(hbuf[t][c+3], wr[c+3], a3);
            }
            dst[(t*WW + w)*NUc + ch] = ((a0 + a1) + (a2 + a3)) * scale;
        }
    }
}

// ---------------------------------------------------------------------------
// NATTEN-2D: 4x8 tile (R8 staging), 512 threads = 16 warps = (head, row).
// Each warp: one row-task of 8 queries processed as 2 chunks of 4
// (qv[24]+oa[24]+sum[4] fits the 128-reg cap -> no spills, 2x warps).
// ---------------------------------------------------------------------------
__global__ void __launch_bounds__(512)
natten_kernel(const float* __restrict__ qsrc,
              const float* __restrict__ ksrc,
              const float* __restrict__ vsrc,
              const float* __restrict__ rpb,
              const float* __restrict__ pw,
              const float* __restrict__ pb,
              const float* __restrict__ qkv_w,
              const float* __restrict__ qkv_b,
              const float* __restrict__ ow,
              const float* __restrict__ ob,
              float* __restrict__ out,
              int mode)
{
    const int i0 = blockIdx.y * 4;
    const int j0 = blockIdx.x * 8;
    extern __shared__ float sm[];
    float* ks   = sm;                           // [28*32][PITCH]
    float* vs   = ks + UROWS*32*PITCH;
    float* rpsh = vs + UROWS*32*PITCH;          // [4][28][49]
    float* ao   = rpsh + 4*RPROWS*49;           // [32][24]
    float* po   = ao + 32*NUc;                  // [32][24]
    float* wsh  = po + 32*NUc;                  // [72*24]
    float* bsh  = wsh + 72*NUc;                 // [72]

    const int tid = threadIdx.x;

    const int si0 = min(max(i0     - 12, 0), TT - KK);
    const int si3 = min(max(i0 + 3 - 12, 0), TT - KK);
    const int nrows = si3 + KK - si0;                      // 25..28
    const int sj_min  = min(max(j0     - 12, 0), WW - KK);
    const int sj_last = min(max(j0 + 7 - 12, 0), WW - KK);
    const int ncols   = sj_last + KK - sj_min;             // <= 32
    const int rmin = si3 - (i0 + 3) + (KK - 1);

    if (mode == 0) {
        for (int x = tid; x < 72*NUc; x += 512) wsh[x] = qkv_w[x];
        if (tid < 72) bsh[tid] = qkv_b[tid];
    }

    for (int idx = tid; idx < 4*RPROWS*49; idx += 512) {
        int hn = idx / (RPROWS*49);
        int rem = idx - hn*(RPROWS*49);
        int rr = rem / 49, cc = rem - rr*49;
        rpsh[idx] = __ldg(rpb + hn*2401 + (rmin + rr)*49 + cc);
    }

    const int npx = nrows * 32;
    for (int spx = tid; spx < npx; spx += 512) {
        int a = spx >> 5, c = spx & 31;
        int cc = min(c, ncols - 1);
        int gpx = (si0 + a)*WW + (sj_min + cc);
        float* kdst = ks + (a*32 + c)*PITCH;
        float* vdst = vs + (a*32 + c)*PITCH;
        const float4* kp = (const float4*)(ksrc + gpx*NUc);
        const float4* vp = (const float4*)(vsrc + gpx*NUc);
        #pragma unroll
        for (int f = 0; f < 6; f++) {
            float4 kd = kp[f];
            *(float2*)(kdst + f*4)     = make_float2(kd.x, kd.y);
            *(float2*)(kdst + f*4 + 2) = make_float2(kd.z, kd.w);
        }
        #pragma unroll
        for (int f = 0; f < 6; f++) {
            float4 vd = vp[f];
            *(float2*)(vdst + f*4)     = make_float2(vd.x, vd.y);
            *(float2*)(vdst + f*4 + 2) = make_float2(vd.z, vd.w);
        }
    }
    __syncthreads();

    const int warp = tid >> 5, lane = tid & 31;
    const int n = warp & 3;             // head
    const int r = warp >> 2;            // row 0..3

    const int i = i0 + r;
    const int sir = min(max(i - 12, 0), TT - KK);
    const int arow = sir - si0;
    const int ra   = (sir - i + (KK - 1)) - rmin;
    const float* rpw = rpsh + n*(RPROWS*49) + ra*49;

    // per-chunk processing: 2 chunks of 4 queries
    for (int chk = 0; chk < 2; chk++) {
        const int p0 = chk*4;

        int   rjp[4];
        float vf [4];
        #pragma unroll
        for (int q = 0; q < 4; q++) {
            int p = p0 + q;
            int sj = min(max(j0 + p - 12, 0), WW - KK);
            int cb = sj - sj_min;
            bool valid = ((unsigned)(lane - cb)) < 25u;
            int rj = (lane - cb) + (sj - (j0 + p) + (KK - 1));
            rjp[q] = min(max(rj, 0), 48);
            vf[q]  = valid ? 1.0f : 0.0f;
        }

        float qv[24];
        #pragma unroll
        for (int q = 0; q < 4; q++) {
            const float2* qp = (const float2*)(qsrc + ((i*WW + j0 + p0 + q)*NUc + n*HDd));
            float2 a0 = qp[0], a1 = qp[1], a2 = qp[2];
            qv[q*6+0]=a0.x; qv[q*6+1]=a0.y;
            qv[q*6+2]=a1.x; qv[q*6+3]=a1.y;
            qv[q*6+4]=a2.x; qv[q*6+5]=a2.y;
        }

        float sum[4];
        float oa[24];
        #pragma unroll
        for (int q = 0; q < 4; q++) sum[q] = 0.f;
        #pragma unroll
        for (int x = 0; x < 24; x++) oa[x] = 0.f;

        #pragma unroll 1
        for (int a = 0; a < KK; a++) {
            const int base = ((arow + a)*32 + lane)*PITCH + n*HDd;
            const float* kp = ks + base;
            const float* vp = vs + base;
            float2 k01 = *(const float2*)(kp);
            float2 k23 = *(const float2*)(kp + 2);
            float2 k45 = *(const float2*)(kp + 4);
            float2 v01 = *(const float2*)(vp);
            float2 v23 = *(const float2*)(vp + 2);
            float2 v45 = *(const float2*)(vp + 4);
            const float* rpr = rpw + a*49;
            #pragma unroll
            for (int q = 0; q < 4; q++) {
                float lg = rpr[rjp[q]];
                lg = fmaf(qv[q*6+0], k01.x, lg);
                lg = fmaf(qv[q*6+1], k01.y, lg);
                lg = fmaf(qv[q*6+2], k23.x, lg);
                lg = fmaf(qv[q*6+3], k23.y, lg);
                lg = fmaf(qv[q*6+4], k45.x, lg);
                lg = fmaf(qv[q*6+5], k45.y, lg);
                float pr = __expf(lg) * vf[q];
                sum[q] += pr;
                oa[q*6+0] = fmaf(pr, v01.x, oa[q*6+0]);
                oa[q*6+1] = fmaf(pr, v01.y, oa[q*6+1]);
                oa[q*6+2] = fmaf(pr, v23.x, oa[q*6+2]);
                oa[q*6+3] = fmaf(pr, v23.y, oa[q*6+3]);
                oa[q*6+4] = fmaf(pr, v45.x, oa[q*6+4]);
                oa[q*6+5] = fmaf(pr, v45.y, oa[q*6+5]);
            }
        }

        #pragma unroll
        for (int q = 0; q < 4; q++) {
            float s  = sum[q];
            float o0 = oa[q*6+0], o1 = oa[q*6+1], o2 = oa[q*6+2];
            float o3 = oa[q*6+3], o4 = oa[q*6+4], o5 = oa[q*6+5];
            #pragma unroll
            for (int off = 16; off > 0; off >>= 1) {
                s  += __shfl_xor_sync(0xffffffffu, s,  off);
                o0 += __shfl_xor_sync(0xffffffffu, o0, off);
                o1 += __shfl_xor_sync(0xffffffffu, o1, off);
                o2 += __shfl_xor_sync(0xffffffffu, o2, off);
                o3 += __shfl_xor_sync(0xffffffffu, o3, off);
                o4 += __shfl_xor_sync(0xffffffffu, o4, off);
                o5 += __shfl_xor_sync(0xffffffffu, o5, off);
            }
            if (lane == 0) {
                float inv = 1.0f / s;
                float* dst = ao + (r*8 + p0 + q)*NUc + n*HDd;
                dst[0]=o0*inv; dst[1]=o1*inv; dst[2]=o2*inv;
                dst[3]=o3*inv; dst[4]=o4*inv; dst[5]=o5*inv;
            }
        }
    }
    __syncthreads();

    // output projection (24x24) for 32 pixels
    for (int idx = tid; idx < 32*NUc; idx += 512) {
        int pp = idx / NUc, oc = idx % NUc;
        float acc = __ldg(pb + oc);
        const float* wrow = pw + oc*NUc;
        #pragma unroll
        for (int ic = 0; ic < NUc; ic++)
            acc = fmaf(ao[pp*NUc + ic], __ldg(wrow + ic), acc);
        po[pp*NUc + oc] = acc;
    }
    __syncthreads();

    if (mode == 0) {
        for (int idx = tid; idx < 32*72; idx += 512) {
            int pp = idx / 72, oc = idx % 72;
            float acc = bsh[oc];
            const float* wrow = wsh + oc*NUc;
            const float* xr = po + pp*NUc;
            #pragma unroll
            for (int c = 0; c < NUc; c++) acc = fmaf(xr[c], wrow[c], acc);
            int e = oc / NUc, ch = oc % NUc;
            int gpx = (i0 + (pp >> 3))*WW + j0 + (pp & 7);
            if      (e == 0) g_q1[gpx*NUc + ch] = acc * QSCALE;
            else if (e == 1) g_k1[gpx*NUc + ch] = acc;
            else             g_v1[gpx*NUc + ch] = acc;
        }
    } else {
        if (tid < 32*5) {
            int pp = tid / 5, rr = tid % 5;
            float acc = __ldg(ob + rr);
            const float* wrow = ow + rr*NUc;
            #pragma unroll
            for (int ic = 0; ic < NUc; ic++)
                acc = fmaf(po[pp*NUc + ic], __ldg(wrow + ic), acc);
            out[((i0 + (pp >> 3))*WW + j0 + (pp & 7))*5 + rr] = acc;
        }
    }
}

// ---------------------------------------------------------------------------
extern "C" void kernel_launch(void* const* d_in, const int* in_sizes, int n_in,
                              void* d_out, int out_size)
{
    const float* features  = (const float*)d_in[0];
    const int*   condition = (const int*)  d_in[1];
    const float* mask      = (const float*)d_in[2];
    const float* emb       = (const float*)d_in[3];
    const float* wih0      = (const float*)d_in[4];
    const float* whh0      = (const float*)d_in[5];
    const float* bih0      = (const float*)d_in[6];
    const float* bhh0      = (const float*)d_in[7];
    const float* wih1      = (const float*)d_in[8];
    const float* whh1      = (const float*)d_in[9];
    const float* bih1      = (const float*)d_in[10];
    const float* bhh1      = (const float*)d_in[11];
    const float* qkv_w     = (const float*)d_in[12];
    const float* qkv_b     = (const float*)d_in[13];
    const float* rpb       = (const float*)d_in[14];
    const float* proj_w    = (const float*)d_in[15];
    const float* proj_b    = (const float*)d_in[16];
    const float* out_w     = (const float*)d_in[17];
    const float* out_b     = (const float*)d_in[18];
    float* out = (float*)d_out;

    float *pq0, *pk0, *pv0, *pq1, *pk1, *pv1;
    cudaGetSymbolAddress((void**)&pq0, g_q0);
    cudaGetSymbolAddress((void**)&pk0, g_k0);
    cudaGetSymbolAddress((void**)&pv0, g_v0);
    cudaGetSymbolAddress((void**)&pq1, g_q1);
    cudaGetSymbolAddress((void**)&pk1, g_k1);
    cudaGetSymbolAddress((void**)&pv1, g_v1);

    const int natten_smem =
        (2*UROWS*32*PITCH + 4*RPROWS*49 + 2*32*NUc + 72*NUc + 72)
        * (int)sizeof(float);
    cudaFuncSetAttribute(natten_kernel,
                         cudaFuncAttributeMaxDynamicSharedMemorySize, natten_smem);

    // 1) fused LSTM + QKV(layer1)
    lstm_kernel<<<WW, 768>>>(features, condition, mask, emb,
                             wih0, whh0, bih0, bhh0,
                             wih1, whh1, bih1, bhh1,
                             qkv_w, qkv_b);

    dim3 ngrid(WW/8, TT/4);   // 11 x 16 = 176 blocks

    // 2) NATTEN layer 1 (+ fused QKV for layer 2)
    natten_kernel<<<ngrid, 512, natten_smem>>>(pq0, pk0, pv0,
                                               rpb, proj_w, proj_b,
                                               qkv_w, qkv_b, out_w, out_b,
                                               nullptr, 0);

    // 3) NATTEN layer 2 (+ fused head) -> d_out
    natten_kernel<<<ngrid, 512, natten_smem>>>(pq1, pk1, pv1,
                                               rpb, proj_w, proj_b,
                                               qkv_w, qkv_b, out_w, out_b,
                                               out, 1);
}